// round 17
// baseline (speedup 1.0000x reference)
#include <cuda_runtime.h>
#include <cuda_bf16.h>
#include <cstdint>
#include <cstddef>

typedef unsigned long long ull;

#define GDIM 64
#define G3 (GDIM*GDIM*GDIM)
#define BATCH 4
#define NPTS 200000
#define MAXPV 35.0f
#define NTILES 8192
#define PSTR 72

// ---------------- scratch (zero-initialized at module load; self-cleaned by k_tile) ----------------
__device__ __align__(16) float g_accum[BATCH*G3*8];
__device__ float g_mm2[BATCH*64*6];
__device__ float g_A1t[7*64];
__device__ float g_c1[64];
__device__ float g_c2[128];
__device__ __align__(16) uint4 g_Wf[128*20];   // fragment-packed hi/lo weights, stride 20 uint4/channel

// ---------------- helpers ----------------
__device__ __forceinline__ void red4(float* addr, float x, float y, float z, float w){
    asm volatile("red.global.add.v4.f32 [%0], {%1,%2,%3,%4};"
                 :: "l"(addr), "f"(x), "f"(y), "f"(z), "f"(w) : "memory");
}
__device__ __forceinline__ void mma_bf16(float& c0, float& c1, float& c2, float& c3,
                                         uint32_t a0, uint32_t a1, uint32_t a2, uint32_t a3,
                                         uint32_t b0, uint32_t b1){
    asm volatile("mma.sync.aligned.m16n8k16.row.col.f32.bf16.bf16.f32 "
                 "{%0,%1,%2,%3}, {%4,%5,%6,%7}, {%8,%9}, {%0,%1,%2,%3};"
                 : "+f"(c0), "+f"(c1), "+f"(c2), "+f"(c3)
                 : "r"(a0), "r"(a1), "r"(a2), "r"(a3), "r"(b0), "r"(b1));
}
__device__ __forceinline__ void cpasync16(unsigned saddr, const void* gaddr){
    asm volatile("cp.async.cg.shared.global [%0], [%1], 16;" :: "r"(saddr), "l"(gaddr));
}
__device__ __forceinline__ void cpasync_commit(){ asm volatile("cp.async.commit_group;"); }
__device__ __forceinline__ void cpasync_wait0(){ asm volatile("cp.async.wait_group 0;"); }
__device__ __forceinline__ uint32_t pack_bf16x2(float a, float b){
    __nv_bfloat16 ba = __float2bfloat16(a);
    __nv_bfloat16 bb = __float2bfloat16(b);
    return (uint32_t)*(uint16_t*)&ba | ((uint32_t)*(uint16_t*)&bb << 16);
}

// ---------------- kernel 1: prep (weights fuse + minmax partials; NO zeroing) ----------------
// block 0: weight fuse; blocks [1,257): minmax partials
__global__ void k_prep(const float* __restrict__ W1, const float* __restrict__ b1,
                       const float* __restrict__ g1, const float* __restrict__ be1,
                       const float* __restrict__ rm1, const float* __restrict__ rv1,
                       const float* __restrict__ W2, const float* __restrict__ b2,
                       const float* __restrict__ g2, const float* __restrict__ be2,
                       const float* __restrict__ rm2, const float* __restrict__ rv2,
                       const float* __restrict__ pc){
    if(blockIdx.x == 0){
        int t = threadIdx.x;
        if(t < 64){
            float s = g1[t] / sqrtf(rv1[t] + 1e-5f);
            g_c1[t] = (b1[t] - rm1[t]) * s + be1[t];
            #pragma unroll
            for(int k = 0; k < 7; k++) g_A1t[k*64 + t] = W1[t*7 + k] * s;
        }
        if(t < 128){
            float s = g2[t] / sqrtf(rv2[t] + 1e-5f);
            g_c2[t] = (b2[t] - rm2[t]) * s + be2[t];
        }
        #pragma unroll
        for(int r = 0; r < 8; r++){
            int fid = t + r*256;
            int c = fid >> 4, rem = fid & 15;
            int ks = rem >> 2, tt = rem & 3;
            float s = g2[c] / sqrtf(rv2[c] + 1e-5f);
            int kwA = ks*8 + tt, kwB = kwA + 4;
            float wa0 = W2[c*64 + 2*kwA    ] * s;
            float wa1 = W2[c*64 + 2*kwA + 1] * s;
            float wb0 = W2[c*64 + 2*kwB    ] * s;
            float wb1 = W2[c*64 + 2*kwB + 1] * s;
            __nv_bfloat16 ha0 = __float2bfloat16(wa0);
            __nv_bfloat16 ha1 = __float2bfloat16(wa1);
            __nv_bfloat16 hb0 = __float2bfloat16(wb0);
            __nv_bfloat16 hb1 = __float2bfloat16(wb1);
            uint4 f;
            f.x = (uint32_t)*(uint16_t*)&ha0 | ((uint32_t)*(uint16_t*)&ha1 << 16);
            f.y = (uint32_t)*(uint16_t*)&hb0 | ((uint32_t)*(uint16_t*)&hb1 << 16);
            f.z = pack_bf16x2(wa0 - __bfloat162float(ha0), wa1 - __bfloat162float(ha1));
            f.w = pack_bf16x2(wb0 - __bfloat162float(hb0), wb1 - __bfloat162float(hb1));
            g_Wf[c*20 + ks*4 + tt] = f;
        }
        return;
    }
    int m = blockIdx.x - 1;             // 0..255
    int b = m >> 6, mloc = m & 63;
    const float* px = pc + b*6*NPTS;
    float mn0= 3.4e38f, mn1= 3.4e38f, mn2= 3.4e38f;
    float mx0=-3.4e38f, mx1=-3.4e38f, mx2=-3.4e38f;
    for(int n = mloc*256 + threadIdx.x; n < NPTS; n += 64*256){
        float x = px[n], y = px[NPTS+n], z = px[2*NPTS+n];
        mn0 = fminf(mn0,x); mx0 = fmaxf(mx0,x);
        mn1 = fminf(mn1,y); mx1 = fmaxf(mx1,y);
        mn2 = fminf(mn2,z); mx2 = fmaxf(mx2,z);
    }
    #pragma unroll
    for(int s = 16; s; s >>= 1){
        mn0 = fminf(mn0, __shfl_xor_sync(~0u, mn0, s));
        mn1 = fminf(mn1, __shfl_xor_sync(~0u, mn1, s));
        mn2 = fminf(mn2, __shfl_xor_sync(~0u, mn2, s));
        mx0 = fmaxf(mx0, __shfl_xor_sync(~0u, mx0, s));
        mx1 = fmaxf(mx1, __shfl_xor_sync(~0u, mx1, s));
        mx2 = fmaxf(mx2, __shfl_xor_sync(~0u, mx2, s));
    }
    __shared__ float wred[8][6];
    int wid = threadIdx.x >> 5;
    if((threadIdx.x & 31) == 0){
        wred[wid][0]=mn0; wred[wid][1]=mn1; wred[wid][2]=mn2;
        wred[wid][3]=mx0; wred[wid][4]=mx1; wred[wid][5]=mx2;
    }
    __syncthreads();
    if(threadIdx.x < 6){
        int c = threadIdx.x;
        bool isMin = c < 3;
        float acc = wred[0][c];
        #pragma unroll
        for(int w = 1; w < 8; w++) acc = isMin ? fminf(acc, wred[w][c]) : fmaxf(acc, wred[w][c]);
        g_mm2[m*6 + c] = acc;
    }
}

// ---------------- kernel 2: voxel scatter (unchanged iteration pattern) ----------------
__global__ void k_voxel(const float* __restrict__ pc){
    int b = blockIdx.y;
    __shared__ float red[6];
    {
        int wid = threadIdx.x >> 5, lid = threadIdx.x & 31;
        if(wid < 6){
            bool isMin = wid < 3;
            float acc = isMin ? 3.4e38f : -3.4e38f;
            for(int m = lid; m < 64; m += 32){
                float v = g_mm2[(b*64 + m)*6 + wid];
                acc = isMin ? fminf(acc, v) : fmaxf(acc, v);
            }
            #pragma unroll
            for(int s = 16; s; s >>= 1){
                float o = __shfl_xor_sync(~0u, acc, s);
                acc = isMin ? fminf(acc, o) : fmaxf(acc, o);
            }
            if(lid == 0) red[wid] = acc;
        }
        __syncthreads();
    }
    float mn0 = red[0], mn1 = red[1], mn2 = red[2];
    float d0 = red[3] - mn0 + 1e-7f;
    float d1 = red[4] - mn1 + 1e-7f;
    float d2 = red[5] - mn2 + 1e-7f;

    const float* p = pc + b*6*NPTS;
    float* acc = g_accum + (size_t)b*G3*8;
    for(int n = blockIdx.x*blockDim.x + threadIdx.x; n < NPTS; n += gridDim.x*blockDim.x){
        float x = p[n], y = p[NPTS+n], z = p[2*NPTS+n];
        float r = p[3*NPTS+n], g = p[4*NPTS+n], bl = p[5*NPTS+n];
        float tx = __fmul_rn(__fdiv_rn(x - mn0, d0), 63.0f);
        float ty = __fmul_rn(__fdiv_rn(y - mn1, d1), 63.0f);
        float tz = __fmul_rn(__fdiv_rn(z - mn2, d2), 63.0f);
        tx = fminf(fmaxf(tx, 0.0f), 62.9999f);
        ty = fminf(fmaxf(ty, 0.0f), 62.9999f);
        tz = fminf(fmaxf(tz, 0.0f), 62.9999f);
        int flat = (((int)tx)*GDIM + (int)ty)*GDIM + (int)tz;
        float* v = acc + (size_t)flat*8;
        red4(v,     x, y, z, 1.0f);
        red4(v + 4, r, g, bl, 0.0f);
    }
}

// ---------------- kernel 3: fused per-tile MLP + masked store + accumulator self-clean ----------------
#define SB_WF    0                       // 40960
#define SB_HHI   40960                   // 18432
#define SB_HLO   59392                   // 18432 -> 77824
#define SB_FEAT  77824                   // -> 81920
#define SB_A1T   81920                   // -> 83712
#define SB_C1    83712                   // -> 83968
#define SB_C2    83968                   // -> 84480
#define SB_PERM  84480                   // -> 84992
#define SB_AUX   84992                   // 16 ints -> 85056
#define SB_BYTES 85056

__global__ void __launch_bounds__(256, 2) k_tile(float* __restrict__ out){
    extern __shared__ char smc[];
    uint4* Wfs = (uint4*)(smc + SB_WF);
    __nv_bfloat16* Hhi = (__nv_bfloat16*)(smc + SB_HHI);
    __nv_bfloat16* Hlo = (__nv_bfloat16*)(smc + SB_HLO);
    float* featS = (float*)(smc + SB_FEAT);
    float* A1tS  = (float*)(smc + SB_A1T);
    float* c1S   = (float*)(smc + SB_C1);
    float* c2S   = (float*)(smc + SB_C2);
    int*   permS = (int*)(smc + SB_PERM);
    int*   auxS  = (int*)(smc + SB_AUX);
    float* oS    = (float*)smc;          // overlay (first 64KB)

    int tid = threadIdx.x;
    int tile = blockIdx.x;
    int b = tile >> 11;
    int vbase = (tile & 2047) << 7;
    float* accw = g_accum + ((size_t)b*G3 + vbase)*8;
    float* ob = out + (size_t)b*128*G3 + vbase;
    float4 z4 = make_float4(0.f,0.f,0.f,0.f);

    // weight prefetch via cp.async, overlapped with phases 1-3
    {
        unsigned sb = (unsigned)__cvta_generic_to_shared(smc);
        #pragma unroll
        for(int r = 0; r < 8; r++){
            int i = tid + r*256;
            int c = i >> 4, q = i & 15;
            cpasync16(sb + SB_WF + (unsigned)(c*20 + q)*16, &g_Wf[c*20 + q]);
        }
        cpasync_commit();
    }

    // phase 1: load accumulators, ballot occupancy, self-clean occupied entries
    float4 p0 = make_float4(0,0,0,0), p1 = make_float4(0,0,0,0);
    int occ = 0;
    if(tid < 128){
        p0 = *(const float4*)(accw + tid*8);
        p1 = *(const float4*)(accw + tid*8 + 4);
        occ = p0.w > 0.f;
        if(occ){
            // zero for next graph replay (module-load state restored)
            *(float4*)(accw + tid*8)     = z4;
            *(float4*)(accw + tid*8 + 4) = z4;
        }
    }
    unsigned bal = __ballot_sync(0xFFFFFFFFu, occ);
    if(tid < 128 && (tid & 31) == 0){
        auxS[tid >> 5] = __popc(bal);
        auxS[8 + (tid >> 5)] = (int)bal;
    }
    __syncthreads();
    int n0 = auxS[0], n1 = auxS[1], n2 = auxS[2], n3 = auxS[3];
    int M = n0 + n1 + n2 + n3;

    if(M == 0){
        for(int i = tid; i < 4096; i += 256){
            int c = i >> 5, q = i & 31;
            __stcs((float4*)(ob + (size_t)c*G3) + q, z4);
        }
        return;
    }

    // quad occupancy mask (warp 0): quad q covers voxels 4q..4q+3
    if(tid < 32){
        unsigned wball = (unsigned)auxS[8 + (tid >> 3)];
        unsigned nib = (wball >> ((tid & 7)*4)) & 0xFu;
        unsigned qb = __ballot_sync(0xFFFFFFFFu, nib != 0u);
        if(tid == 0) auxS[12] = (int)qb;
    }

    // phase 2: features + perm + small consts
    if(occ){
        float dn = fmaxf(p0.w, 1.0f);
        float* f = featS + tid*8;
        f[0] = __fdiv_rn(p0.x, dn);
        f[1] = __fdiv_rn(p0.y, dn);
        f[2] = __fdiv_rn(p0.z, dn);
        f[3] = __fdiv_rn(fminf(p0.w, MAXPV), MAXPV);
        f[4] = __fdiv_rn(p1.x, dn);
        f[5] = __fdiv_rn(p1.y, dn);
        f[6] = __fdiv_rn(p1.z, dn);
        f[7] = 0.f;
        int w = tid >> 5;
        int off = (w > 0 ? n0 : 0) + (w > 1 ? n1 : 0) + (w > 2 ? n2 : 0);
        permS[off + __popc(bal & ((1u << (tid & 31)) - 1u))] = tid;
    }
    for(int i = tid; i < 448; i += 256) A1tS[i] = g_A1t[i];
    if(tid < 64)  c1S[tid] = g_c1[tid];
    if(tid < 128) c2S[tid] = g_c2[tid];
    __syncthreads();

    // phase 3: layer 1 for occupied slots -> bf16 hi/lo planes
    for(int i = tid; i < M*32; i += 256){
        int slot = i >> 5, jp = (i & 31)*2;
        int v = permS[slot];
        float s0 = c1S[jp], s1 = c1S[jp+1];
        const float* f = featS + v*8;
        #pragma unroll
        for(int k = 0; k < 7; k++){
            float fv = f[k];
            s0 = fmaf(fv, A1tS[k*64 + jp],   s0);
            s1 = fmaf(fv, A1tS[k*64 + jp+1], s1);
        }
        float h0 = fmaxf(s0, 0.f), h1 = fmaxf(s1, 0.f);
        __nv_bfloat16 h0h = __float2bfloat16(h0);
        __nv_bfloat16 h1h = __float2bfloat16(h1);
        __nv_bfloat16 h0l = __float2bfloat16(h0 - __bfloat162float(h0h));
        __nv_bfloat16 h1l = __float2bfloat16(h1 - __bfloat162float(h1h));
        uint32_t hiw = (uint32_t)*(uint16_t*)&h0h | ((uint32_t)*(uint16_t*)&h1h << 16);
        uint32_t low = (uint32_t)*(uint16_t*)&h0l | ((uint32_t)*(uint16_t*)&h1l << 16);
        *(uint32_t*)(Hhi + slot*PSTR + jp) = hiw;
        *(uint32_t*)(Hlo + slot*PSTR + jp) = low;
    }
    cpasync_wait0();
    __syncthreads();

    // phase 4: HMMA jobs. job j: chunk=j>>1 (16 slots), channel half=(j&1)*64.
    int nchunk = (M + 15) >> 4;
    int njobs = nchunk*2;
    int w = tid >> 5, lane = tid & 31;
    int g = lane >> 2, t = lane & 3;

    float accr[2][8][4];
    #pragma unroll
    for(int jj = 0; jj < 2; jj++)
        #pragma unroll
        for(int nt = 0; nt < 8; nt++)
            #pragma unroll
            for(int r = 0; r < 4; r++) accr[jj][nt][r] = 0.f;

    #pragma unroll
    for(int jj = 0; jj < 2; jj++){
        int j = w + jj*8;
        if(j < njobs){
            int chunk = j >> 1, cb = (j & 1)*64;
            int m0 = chunk*16;
            const __nv_bfloat16* hArow = Hhi + (m0+g)*PSTR;
            const __nv_bfloat16* hBrow = Hhi + (m0+g+8)*PSTR;
            const __nv_bfloat16* lArow = Hlo + (m0+g)*PSTR;
            const __nv_bfloat16* lBrow = Hlo + (m0+g+8)*PSTR;
            #pragma unroll
            for(int ks = 0; ks < 4; ks++){
                int kc = ks*16 + 2*t;
                uint32_t ah0 = *(const uint32_t*)(hArow + kc);
                uint32_t ah1 = *(const uint32_t*)(hBrow + kc);
                uint32_t ah2 = *(const uint32_t*)(hArow + kc + 8);
                uint32_t ah3 = *(const uint32_t*)(hBrow + kc + 8);
                uint32_t al0 = *(const uint32_t*)(lArow + kc);
                uint32_t al1 = *(const uint32_t*)(lBrow + kc);
                uint32_t al2 = *(const uint32_t*)(lArow + kc + 8);
                uint32_t al3 = *(const uint32_t*)(lBrow + kc + 8);
                #pragma unroll
                for(int nt = 0; nt < 8; nt++){
                    uint4 wf = Wfs[(cb + nt*8 + g)*20 + ks*4 + t];
                    mma_bf16(accr[jj][nt][0], accr[jj][nt][1], accr[jj][nt][2], accr[jj][nt][3],
                             ah0, ah1, ah2, ah3, wf.x, wf.y);
                    mma_bf16(accr[jj][nt][0], accr[jj][nt][1], accr[jj][nt][2], accr[jj][nt][3],
                             al0, al1, al2, al3, wf.x, wf.y);
                    mma_bf16(accr[jj][nt][0], accr[jj][nt][1], accr[jj][nt][2], accr[jj][nt][3],
                             ah0, ah1, ah2, ah3, wf.z, wf.w);
                }
            }
        }
    }
    unsigned qmask = (unsigned)auxS[12];
    __syncthreads();               // Wf + H dead from here (perm/aux outside 64KB overlay)

    // phase 5: masked zero, scatter, masked store
    for(int i = tid; i < 4096; i += 256){
        int c = i >> 5, vq = i & 31;
        if((qmask >> vq) & 1u)
            *(float4*)(oS + c*128 + ((vq ^ ((c >> 3) & 15)) << 2)) = z4;
    }
    __syncthreads();

    #pragma unroll
    for(int jj = 0; jj < 2; jj++){
        int j = w + jj*8;
        if(j < njobs){
            int chunk = j >> 1, cb = (j & 1)*64;
            int slotA = chunk*16 + g;
            int slotB = slotA + 8;
            int vA = (slotA < M) ? permS[slotA] : -1;
            int vB = (slotB < M) ? permS[slotB] : -1;
            #pragma unroll
            for(int nt = 0; nt < 8; nt++){
                int ch = cb + nt*8 + 2*t;
                int sw = (ch >> 3) & 15;
                float b0 = c2S[ch], b1 = c2S[ch+1];
                if(vA >= 0){
                    int idx = (((vA >> 2) ^ sw) << 2) + (vA & 3);
                    oS[ch*128 + idx]     = fmaxf(accr[jj][nt][0] + b0, 0.f);
                    oS[(ch+1)*128 + idx] = fmaxf(accr[jj][nt][1] + b1, 0.f);
                }
                if(vB >= 0){
                    int idx = (((vB >> 2) ^ sw) << 2) + (vB & 3);
                    oS[ch*128 + idx]     = fmaxf(accr[jj][nt][2] + b0, 0.f);
                    oS[(ch+1)*128 + idx] = fmaxf(accr[jj][nt][3] + b1, 0.f);
                }
            }
        }
    }
    __syncthreads();

    for(int i = tid; i < 4096; i += 256){
        int c = i >> 5, vq = i & 31;
        float4 v = ((qmask >> vq) & 1u)
            ? *(const float4*)(oS + c*128 + ((vq ^ ((c >> 3) & 15)) << 2)) : z4;
        __stcs((float4*)(ob + (size_t)c*G3) + vq, v);
    }
}

// ---------------- launch ----------------
extern "C" void kernel_launch(void* const* d_in, const int* in_sizes, int n_in,
                              void* d_out, int out_size){
    const float* pc  = (const float*)d_in[0];
    const float* W1  = (const float*)d_in[1];
    const float* b1  = (const float*)d_in[2];
    const float* g1  = (const float*)d_in[3];
    const float* be1 = (const float*)d_in[4];
    const float* rm1 = (const float*)d_in[5];
    const float* rv1 = (const float*)d_in[6];
    const float* W2  = (const float*)d_in[7];
    const float* b2  = (const float*)d_in[8];
    const float* g2  = (const float*)d_in[9];
    const float* be2 = (const float*)d_in[10];
    const float* rm2 = (const float*)d_in[11];
    const float* rv2 = (const float*)d_in[12];

    cudaFuncSetAttribute(k_tile, cudaFuncAttributeMaxDynamicSharedMemorySize, SB_BYTES);

    k_prep<<<257, 256>>>(W1,b1,g1,be1,rm1,rv1,W2,b2,g2,be2,rm2,rv2, pc);
    k_voxel<<<dim3(782,4), 256>>>(pc);
    k_tile<<<NTILES, 256, SB_BYTES>>>((float*)d_out);
}